// round 7
// baseline (speedup 1.0000x reference)
#include <cuda_runtime.h>
#include <math.h>

#define HID   2048
#define VOCAB 50257
#define NB    148
#define NT    1024
#define NWARPS (NB * 32)   // 4736 warps grid-wide

// Scratch (no cudaMalloc allowed)
__device__ float        g_gi[3 * HID];
__device__ float        g_gh[3 * HID];
__device__ float        g_hnew[HID];
__device__ float        g_logits[VOCAB];
__device__ unsigned int g_max_u;
__device__ float        g_sum;
__device__ unsigned int g_bar;    // monotone grid-barrier counter
__device__ unsigned int g_done;   // end-of-kernel reset counter

// Grid barrier: all NB blocks co-resident (grid == #SMs), so spinning is safe.
__device__ __forceinline__ void grid_barrier(unsigned int target)
{
    __syncthreads();
    if (threadIdx.x == 0) {
        __threadfence();                      // release this block's stores
        atomicAdd(&g_bar, 1u);
        volatile unsigned int* p = &g_bar;
        while (*p < target) { __nanosleep(32); }
        __threadfence();                      // acquire other blocks' stores
    }
    __syncthreads();
}

__global__ void __launch_bounds__(NT, 1) fused_kernel(
    const int*   __restrict__ idx,
    const float* __restrict__ hidden,
    const float* __restrict__ embed,
    const float* __restrict__ w_ih,
    const float* __restrict__ w_hh,
    const float* __restrict__ b_ih,
    const float* __restrict__ b_hh,
    const float* __restrict__ w_out,
    const float* __restrict__ b_out,
    float*       __restrict__ out,
    float*       __restrict__ hnew_out)   // may be null
{
    __shared__ float4 s_x[HID / 4];   // 8 KB: embed row (later reused for h_new)
    __shared__ float4 s_h[HID / 4];   // 8 KB: hidden
    __shared__ float  s_red[32];

    const int tid  = threadIdx.x;
    const int lane = tid & 31;
    const int warp = tid >> 5;
    const int bid  = blockIdx.x;

    // ---- stage x (embed row) and h into smem: one float4 per thread ----
    {
        const int token = idx[0];
        const float4* x4 = (const float4*)(embed + (size_t)token * HID);
        const float4* h4 = (const float4*)hidden;
        if (tid < HID / 4)           s_x[tid]           = x4[tid];
        else if (tid < 2 * (HID/4))  s_h[tid - HID/4]   = h4[tid - HID/4];
    }
    __syncthreads();

    // ================= Phase 1: gate GEMVs (12288 virtual rows) ==========
    for (int vrow = bid * 32 + warp; vrow < 6 * HID; vrow += NWARPS) {
        const bool is_ih = vrow < 3 * HID;
        const int  row   = is_ih ? vrow : vrow - 3 * HID;
        const float4* w4 = (const float4*)((is_ih ? w_ih : w_hh) + (size_t)row * HID);
        const float4* sv = is_ih ? s_x : s_h;

        float acc = 0.0f;
        #pragma unroll
        for (int j = 0; j < 16; j++) {
            const int k = lane + 32 * j;
            const float4 w = w4[k];
            const float4 v = sv[k];
            acc += w.x*v.x + w.y*v.y + w.z*v.z + w.w*v.w;
        }
        #pragma unroll
        for (int o = 16; o; o >>= 1)
            acc += __shfl_xor_sync(0xffffffffu, acc, o);

        if (lane == 0) {
            if (is_ih) g_gi[row] = acc;
            else       g_gh[row] = acc;
        }
    }

    grid_barrier(1 * NB);

    // ================= Phase 2: elementwise gate math =====================
    // i = bid + NB*tid covers 0..2047 with ~14 active threads per block.
    for (int i = bid + NB * tid; i < HID; i += NB * NT) {
        const float gir = g_gi[i]         + b_ih[i];
        const float giz = g_gi[HID + i]   + b_ih[HID + i];
        const float gin = g_gi[2*HID + i] + b_ih[2*HID + i];
        const float ghr = g_gh[i]         + b_hh[i];
        const float ghz = g_gh[HID + i]   + b_hh[HID + i];
        const float ghn = g_gh[2*HID + i] + b_hh[2*HID + i];

        const float r  = 1.0f / (1.0f + expf(-(gir + ghr)));
        const float z  = 1.0f / (1.0f + expf(-(giz + ghz)));
        const float n  = tanhf(gin + r * ghn);
        const float hn = (1.0f - z) * n + z * hidden[i];

        g_hnew[i] = hn;
        if (hnew_out) hnew_out[i] = hn;
    }
    if (bid == 0 && tid == 0) { g_max_u = 0u; g_sum = 0.0f; }

    grid_barrier(2 * NB);

    // ---- stage h_new into smem (reuse s_x) ----
    if (tid < HID / 4) s_x[tid] = ((const float4*)g_hnew)[tid];
    __syncthreads();

    // ================= Phase 3: logits + running max ======================
    float lmax = 0.0f;
    for (int row = bid * 32 + warp; row < VOCAB; row += NWARPS) {
        const float4* w4 = (const float4*)(w_out + (size_t)row * HID);
        float acc = 0.0f;
        #pragma unroll
        for (int j = 0; j < 16; j++) {
            const int k = lane + 32 * j;
            const float4 w = w4[k];
            const float4 h = s_x[k];
            acc += w.x*h.x + w.y*h.y + w.z*h.z + w.w*h.w;
        }
        #pragma unroll
        for (int o = 16; o; o >>= 1)
            acc += __shfl_xor_sync(0xffffffffu, acc, o);
        if (lane == 0) {
            const float l = fmaxf(acc + b_out[row], 0.0f);
            g_logits[row] = l;
            lmax = fmaxf(lmax, l);
        }
    }
    // block max -> global atomicMax (uint trick valid: all values >= 0)
    #pragma unroll
    for (int o = 16; o; o >>= 1)
        lmax = fmaxf(lmax, __shfl_xor_sync(0xffffffffu, lmax, o));
    if (lane == 0) s_red[warp] = lmax;
    __syncthreads();
    if (tid == 0) {
        float m = s_red[0];
        #pragma unroll
        for (int w = 1; w < 32; w++) m = fmaxf(m, s_red[w]);
        atomicMax(&g_max_u, __float_as_uint(m));
    }

    grid_barrier(3 * NB);

    // ================= Phase 4: sum of exp(l - max) =======================
    const float m = __uint_as_float(g_max_u);
    const int   v = bid * NT + tid;            // 151552 threads >= VOCAB
    float lv = 0.0f;
    float s  = 0.0f;
    if (v < VOCAB) {
        lv = g_logits[v];
        s  = expf(lv - m);
    }
    #pragma unroll
    for (int o = 16; o; o >>= 1)
        s += __shfl_xor_sync(0xffffffffu, s, o);
    if (lane == 0) s_red[warp] = s;
    __syncthreads();
    if (tid == 0) {
        float t = s_red[0];
        #pragma unroll
        for (int w = 1; w < 32; w++) t += s_red[w];
        atomicAdd(&g_sum, t);
    }

    grid_barrier(4 * NB);

    // ================= Phase 5: finalize ==================================
    if (v < VOCAB)
        out[v] = lv - m - logf(g_sum);

    // ---- reset barrier counters for the next graph replay ----
    __syncthreads();
    if (tid == 0) {
        if (atomicAdd(&g_done, 1u) == NB - 1u) {
            g_done = 0u;
            __threadfence();
            g_bar = 0u;
        }
    }
}

// ---------------------------------------------------------------------------
extern "C" void kernel_launch(void* const* d_in, const int* in_sizes, int n_in,
                              void* d_out, int out_size)
{
    const int*   idx    = (const int*)  d_in[0];
    const float* hidden = (const float*)d_in[1];
    const float* embed  = (const float*)d_in[2];
    const float* w_ih   = (const float*)d_in[3];
    const float* w_hh   = (const float*)d_in[4];
    const float* b_ih   = (const float*)d_in[5];
    const float* b_hh   = (const float*)d_in[6];
    const float* w_out  = (const float*)d_in[7];
    const float* b_out  = (const float*)d_in[8];

    float* out = (float*)d_out;
    float* hnew_out = (out_size >= VOCAB + HID) ? (out + VOCAB) : nullptr;

    fused_kernel<<<NB, NT>>>(idx, hidden, embed, w_ih, w_hh, b_ih, b_hh,
                             w_out, b_out, out, hnew_out);
}